// round 11
// baseline (speedup 1.0000x reference)
#include <cuda_runtime.h>
#include <cuda_bf16.h>
#include <cstdint>

#define NTOK 4096
#define CCH 512
#define NH 8
#define HD 64
#define MQKV 1536

// Scratch (device globals; no runtime allocation allowed)
__device__ float g_qkv[MQKV * NTOK];     // rows 0..511 q*scale (fp32), 512..1023 K (tf32-rounded)
__device__ uint32_t g_v[512 * 2048];     // V bf16x2: [channel(512)][jpair(2048)]
__device__ float g_att[CCH * NTOK];      // [C, N] attention output (tf32-rounded)

__device__ __forceinline__ uint32_t f2tf32(float x) {
    uint32_t r;
    asm("cvt.rna.tf32.f32 %0, %1;" : "=r"(r) : "f"(x));
    return r;
}
__device__ __forceinline__ float f2tf32f(float x) {
    return __uint_as_float(f2tf32(x));
}
__device__ __forceinline__ uint32_t pack_bf16x2(float lo, float hi) {
    uint32_t r;
    asm("cvt.rn.bf16x2.f32 %0, %1, %2;" : "=r"(r) : "f"(hi), "f"(lo));
    return r;
}
__device__ __forceinline__ float exp2_fast(float x) {
    float y;
    asm("ex2.approx.ftz.f32 %0, %1;" : "=f"(y) : "f"(x));
    return y;
}
__device__ __forceinline__ void mma_tf32(float c[4], const uint32_t a[4],
                                         uint32_t b0, uint32_t b1) {
    asm volatile(
        "mma.sync.aligned.m16n8k8.row.col.f32.tf32.tf32.f32 "
        "{%0,%1,%2,%3}, {%4,%5,%6,%7}, {%8,%9}, {%0,%1,%2,%3};"
        : "+f"(c[0]), "+f"(c[1]), "+f"(c[2]), "+f"(c[3])
        : "r"(a[0]), "r"(a[1]), "r"(a[2]), "r"(a[3]), "r"(b0), "r"(b1));
}
__device__ __forceinline__ void mma_bf16(float c[4], const uint32_t a[4],
                                         uint32_t b0, uint32_t b1) {
    asm volatile(
        "mma.sync.aligned.m16n8k16.row.col.f32.bf16.bf16.f32 "
        "{%0,%1,%2,%3}, {%4,%5,%6,%7}, {%8,%9}, {%0,%1,%2,%3};"
        : "+f"(c[0]), "+f"(c[1]), "+f"(c[2]), "+f"(c[3])
        : "r"(a[0]), "r"(a[1]), "r"(a[2]), "r"(a[3]), "r"(b0), "r"(b1));
}
__device__ __forceinline__ uint32_t smem_u32(const void* p) {
    uint32_t a;
    asm("{ .reg .u64 t; cvta.to.shared.u64 t, %1; cvt.u32.u64 %0, t; }"
        : "=r"(a) : "l"(p));
    return a;
}
__device__ __forceinline__ void cp16(uint32_t dst, const void* src) {
    asm volatile("cp.async.ca.shared.global [%0], [%1], 16;" :: "r"(dst), "l"(src));
}

// ---------------------------------------------------------------------------
// Tensor-core GEMM, cp.async double-buffered (round-8 proven version).
// Raw fp32 operands fed to HMMA.tf32 (upper-19-bit truncation) — pre-round
// pass eliminated.
// flags bit0 = qkv mode (Q scaled, K tf32-rounded, V -> g_v bf16x2),
// bit1 = bias+residual, bit3 = B from g_att (else param B).
// ---------------------------------------------------------------------------
#define ASTR 36
#define BSTR 136
#define AFL (128 * ASTR)
#define BFL (32 * BSTR)

__global__ __launch_bounds__(256, 2) void gemm_tc(const float* __restrict__ Ain,
                                                  const float* __restrict__ Bin,
                                                  float* __restrict__ Cg,
                                                  const float* __restrict__ bias,
                                                  const float* __restrict__ res,
                                                  int flags) {
    extern __shared__ float smf[];
    const uint32_t sb = smem_u32(smf);

    const float* A = Ain;
    const float* B = (flags & 8) ? g_att : Bin;
    float* C = (flags & 1) ? g_qkv : Cg;

    const int t = threadIdx.x, lane = t & 31, w = t >> 5;
    const int g = lane >> 2, q4 = lane & 3;
    const int mw = (w >> 1) * 32;
    const int nw = (w & 1) * 64;
    const int m0 = blockIdx.y * 128, n0 = blockIdx.x * 128;

    float c[2][8][4] = {};

    int arow[4], acof[4], bk[4], bcof[4];
#pragma unroll
    for (int r = 0; r < 4; r++) {
        int cid = t + 256 * r;
        arow[r] = cid >> 3;  acof[r] = (cid & 7) * 4;
        bk[r]   = cid >> 5;  bcof[r] = (cid & 31) * 4;
    }

#pragma unroll
    for (int r = 0; r < 4; r++)
        cp16(sb + (arow[r] * ASTR + acof[r]) * 4,
             &A[(m0 + arow[r]) * 512 + acof[r]]);
#pragma unroll
    for (int r = 0; r < 4; r++)
        cp16(sb + 36864 + (bk[r] * BSTR + bcof[r]) * 4,
             &B[bk[r] * NTOK + n0 + bcof[r]]);
    asm volatile("cp.async.commit_group;" ::: "memory");

    for (int it = 0; it < 16; it++) {
        const int cur = it & 1;
        asm volatile("cp.async.wait_group 0;" ::: "memory");
        __syncthreads();

        if (it < 15) {
            const int k0 = (it + 1) * 32;
            const uint32_t ad = sb + ((cur ^ 1) ? 18432u : 0u);
            const uint32_t bd = sb + 36864 + ((cur ^ 1) ? 17408u : 0u);
#pragma unroll
            for (int r = 0; r < 4; r++)
                cp16(ad + (arow[r] * ASTR + acof[r]) * 4,
                     &A[(m0 + arow[r]) * 512 + k0 + acof[r]]);
#pragma unroll
            for (int r = 0; r < 4; r++)
                cp16(bd + (bk[r] * BSTR + bcof[r]) * 4,
                     &B[(k0 + bk[r]) * NTOK + n0 + bcof[r]]);
            asm volatile("cp.async.commit_group;" ::: "memory");
        }

        const float* As = smf + cur * AFL;
        const float* Bs = smf + 2 * AFL + cur * BFL;
#pragma unroll
        for (int kk = 0; kk < 32; kk += 8) {
            uint32_t af[2][4], bf[8][2];
#pragma unroll
            for (int mt = 0; mt < 2; mt++) {
                int am = (mw + g + mt * 16) * ASTR + kk + q4;
                af[mt][0] = __float_as_uint(As[am]);
                af[mt][1] = __float_as_uint(As[am + 8 * ASTR]);
                af[mt][2] = __float_as_uint(As[am + 4]);
                af[mt][3] = __float_as_uint(As[am + 8 * ASTR + 4]);
            }
            int br = (kk + q4) * BSTR + nw + g;
#pragma unroll
            for (int jt = 0; jt < 8; jt++) {
                bf[jt][0] = __float_as_uint(Bs[br + jt * 8]);
                bf[jt][1] = __float_as_uint(Bs[br + 4 * BSTR + jt * 8]);
            }
#pragma unroll
            for (int mt = 0; mt < 2; mt++)
#pragma unroll
                for (int jt = 0; jt < 8; jt++)
                    mma_tf32(c[mt][jt], af[mt], bf[jt][0], bf[jt][1]);
        }
    }

    const int mode = (flags & 1) ? (m0 >> 9) : 3;   // 0=Q 1=K 2=V 3=generic
    if (mode == 2) {
#pragma unroll
        for (int mt = 0; mt < 2; mt++) {
#pragma unroll
            for (int jt = 0; jt < 8; jt++) {
                int row = m0 + mw + mt * 16 + g - 1024;
                int jp = (n0 + nw + jt * 8 + q4 * 2) >> 1;
                g_v[row * 2048 + jp]       = pack_bf16x2(c[mt][jt][0], c[mt][jt][1]);
                g_v[(row + 8) * 2048 + jp] = pack_bf16x2(c[mt][jt][2], c[mt][jt][3]);
            }
        }
        return;
    }
    // Q scale folds hd^-0.5 * log2(e); K rows stored tf32-rounded
    const float sc = (mode == 0) ? 0.18033688011112042f : 1.0f;
#pragma unroll
    for (int mt = 0; mt < 2; mt++) {
#pragma unroll
        for (int jt = 0; jt < 8; jt++) {
            int row = m0 + mw + mt * 16 + g;
            int col = n0 + nw + jt * 8 + q4 * 2;
            float2 lo = make_float2(c[mt][jt][0] * sc, c[mt][jt][1] * sc);
            float2 hi = make_float2(c[mt][jt][2] * sc, c[mt][jt][3] * sc);
            if (mode == 1) {
                lo.x = f2tf32f(lo.x); lo.y = f2tf32f(lo.y);
                hi.x = f2tf32f(hi.x); hi.y = f2tf32f(hi.y);
            }
            if (flags & 2) {
                float b0v = bias[row], b1v = bias[row + 8];
                float2 r0 = *(const float2*)&res[row * NTOK + col];
                float2 r1 = *(const float2*)&res[(row + 8) * NTOK + col];
                lo.x += b0v + r0.x; lo.y += b0v + r0.y;
                hi.x += b1v + r1.x; hi.y += b1v + r1.y;
            }
            *(float2*)&C[row * NTOK + col] = lo;
            *(float2*)&C[(row + 8) * NTOK + col] = hi;
        }
    }
}

// ---------------------------------------------------------------------------
// Flash attention (round-8 proven version + hoisted l-reduction):
// BM=128, tf32 S (m16n8k8) + bf16 PV (m16n8k16), double-buffered K/V,
// one sync/iter, transient staging regs, no-max exp2 softmax.
// Dynamic smem: K 2x16KB + V 2x10KB = 53248 B.
// ---------------------------------------------------------------------------
__global__ __launch_bounds__(256, 2) void flash_attn() {
    extern __shared__ char sm[];
    float*    Kf = (float*)sm;                      // [2][32*128] tf32
    uint32_t* Vf = (uint32_t*)(sm + 32768);         // [2][64*40] bf16x2

    const int t = threadIdx.x;
    const int w = t >> 5;
    const int lane = t & 31;
    const int g = lane >> 2;
    const int q4 = lane & 3;
    const int i0 = blockIdx.x * 128;
    const int h  = blockIdx.y;

    const float* qrow = g_qkv + (h * HD) * NTOK;
    const float* krow = g_qkv + (CCH + h * HD) * NTOK;

    // ---- Q fragments from global (once)
    uint32_t Qa[8][4];
    {
        const float* qb = qrow + i0 + w * 16 + g;
#pragma unroll
        for (int kc = 0; kc < 8; kc++) {
            int kr = (kc * 8 + q4) * NTOK;
            Qa[kc][0] = f2tf32(qb[kr]);
            Qa[kc][1] = f2tf32(qb[kr + 8]);
            Qa[kc][2] = f2tf32(qb[kr + 4 * NTOK]);
            Qa[kc][3] = f2tf32(qb[kr + 4 * NTOK + 8]);
        }
    }

    // ---- staging address constants
    const int ks = w * 8 + (lane >> 2);
    const int q4s = ks & 3;
    const int halfs = (lane >> 4) & 1;
    const float* srcK = krow + ks * NTOK + (lane & 3) * 4;
    int dK[4];
#pragma unroll
    for (int it = 0; it < 4; it++) {
        int jt = ((lane & 3) + 4 * it) >> 1;
        dK[it] = (w * 4 + q4s) * 128 + (lane & 1) * 64
               + (((2 * halfs + (jt >> 2)) ^ q4s) << 2) + (jt & 3);
    }
    const uint32_t* srcV = g_v + (h * HD + w) * 2048 + lane;
    const int dVbase = w * 40 + (lane >> 3) * 8 + (lane & 3) * 2 + ((lane >> 2) & 1);

    // ---- prologue: stage tile 0 into buffer 0
    {
        float4 kr[4];
        uint32_t vr[8];
#pragma unroll
        for (int it = 0; it < 4; it++) kr[it] = *(const float4*)(srcK + 16 * it);
#pragma unroll
        for (int it = 0; it < 8; it++) vr[it] = srcV[it * 16384];
#pragma unroll
        for (int it = 0; it < 4; it++) {
            int d0 = dK[it];
            Kf[d0] = kr[it].x; Kf[d0 + 16] = kr[it].y;
            Kf[d0 + 32] = kr[it].z; Kf[d0 + 48] = kr[it].w;
        }
#pragma unroll
        for (int it = 0; it < 8; it++) Vf[dVbase + 320 * it] = vr[it];
    }
    __syncthreads();

    float O[8][4] = {};
    float l0 = 0.f, l1 = 0.f;     // per-lane partials; reduced after the loop

    for (int kt = 0; kt < 64; kt++) {
        const int cur = kt & 1;

        if (kt < 63) {
            const float* pk = srcK + (kt + 1) * 64;
            const uint32_t* pv = srcV + (kt + 1) * 32;
            float4 kr[4];
            uint32_t vr[8];
#pragma unroll
            for (int it = 0; it < 4; it++) kr[it] = *(const float4*)(pk + 16 * it);
#pragma unroll
            for (int it = 0; it < 8; it++) vr[it] = pv[it * 16384];
            const int kofs = (cur ^ 1) * 4096, vofs = (cur ^ 1) * 2560;
#pragma unroll
            for (int it = 0; it < 4; it++) {
                int d0 = kofs + dK[it];
                Kf[d0] = kr[it].x; Kf[d0 + 16] = kr[it].y;
                Kf[d0 + 32] = kr[it].z; Kf[d0 + 48] = kr[it].w;
            }
#pragma unroll
            for (int it = 0; it < 8; it++) Vf[vofs + dVbase + 320 * it] = vr[it];
        }

        // ---- S = Q K^T (tf32)
        const float* Kc = Kf + cur * 4096;
        float S[8][4] = {};
#pragma unroll
        for (int kc = 0; kc < 8; kc++) {
            const float4* kp = (const float4*)(Kc + (kc * 4 + q4) * 128 + g * 16);
            float4 L0 = kp[0 ^ q4], L1 = kp[1 ^ q4], L2 = kp[2 ^ q4], L3 = kp[3 ^ q4];
            mma_tf32(S[0], Qa[kc], __float_as_uint(L0.x), __float_as_uint(L2.x));
            mma_tf32(S[1], Qa[kc], __float_as_uint(L0.y), __float_as_uint(L2.y));
            mma_tf32(S[2], Qa[kc], __float_as_uint(L0.z), __float_as_uint(L2.z));
            mma_tf32(S[3], Qa[kc], __float_as_uint(L0.w), __float_as_uint(L2.w));
            mma_tf32(S[4], Qa[kc], __float_as_uint(L1.x), __float_as_uint(L3.x));
            mma_tf32(S[5], Qa[kc], __float_as_uint(L1.y), __float_as_uint(L3.y));
            mma_tf32(S[6], Qa[kc], __float_as_uint(L1.z), __float_as_uint(L3.z));
            mma_tf32(S[7], Qa[kc], __float_as_uint(L1.w), __float_as_uint(L3.w));
        }

        // ---- no-max softmax (per-lane partial sums; shfl hoisted out of loop)
#pragma unroll
        for (int jt = 0; jt < 8; jt++) {
            S[jt][0] = exp2_fast(S[jt][0]);
            S[jt][1] = exp2_fast(S[jt][1]);
            S[jt][2] = exp2_fast(S[jt][2]);
            S[jt][3] = exp2_fast(S[jt][3]);
            l0 += S[jt][0] + S[jt][1];
            l1 += S[jt][2] + S[jt][3];
        }

        // ---- O += P V (bf16), C-frag -> A-frag register reuse
        const uint32_t* Vc = Vf + cur * 2560;
#pragma unroll
        for (int kc2 = 0; kc2 < 4; kc2++) {
            uint32_t Pa[4];
            Pa[0] = pack_bf16x2(S[2 * kc2][0],     S[2 * kc2][1]);
            Pa[1] = pack_bf16x2(S[2 * kc2][2],     S[2 * kc2][3]);
            Pa[2] = pack_bf16x2(S[2 * kc2 + 1][0], S[2 * kc2 + 1][1]);
            Pa[3] = pack_bf16x2(S[2 * kc2 + 1][2], S[2 * kc2 + 1][3]);
#pragma unroll
            for (int nt = 0; nt < 8; nt++) {
                uint2 bv = *(const uint2*)(Vc + (nt * 8 + g) * 40 + kc2 * 8 + q4 * 2);
                mma_bf16(O[nt], Pa, bv.x, bv.y);
            }
        }
        __syncthreads();
    }

    // ---- final l reduction (hoisted; sum is linear)
    l0 += __shfl_xor_sync(0xffffffffu, l0, 1);
    l0 += __shfl_xor_sync(0xffffffffu, l0, 2);
    l1 += __shfl_xor_sync(0xffffffffu, l1, 1);
    l1 += __shfl_xor_sync(0xffffffffu, l1, 2);

    // ---- normalize + store (tf32-rounded for out-proj raw staging)
    float inv0 = 1.0f / l0, inv1 = 1.0f / l1;
#pragma unroll
    for (int nt = 0; nt < 8; nt++) {
        float* p = g_att + (h * HD + nt * 8 + q4 * 2) * NTOK + i0 + w * 16 + g;
        p[0]        = f2tf32f(O[nt][0] * inv0);
        p[NTOK]     = f2tf32f(O[nt][1] * inv0);
        p[8]        = f2tf32f(O[nt][2] * inv1);
        p[NTOK + 8] = f2tf32f(O[nt][3] * inv1);
    }
}

extern "C" void kernel_launch(void* const* d_in, const int* in_sizes, int n_in,
                              void* d_out, int out_size) {
    const float* x     = (const float*)d_in[0];
    const float* w_qkv = (const float*)d_in[1];
    const float* w_out = (const float*)d_in[2];
    const float* b_out = (const float*)d_in[3];
    float* out = (float*)d_out;

    cudaFuncSetAttribute(flash_attn, cudaFuncAttributeMaxDynamicSharedMemorySize, 53248);
    cudaFuncSetAttribute(gemm_tc, cudaFuncAttributeMaxDynamicSharedMemorySize, 71680);

    gemm_tc<<<dim3(32, 12), 256, 71680>>>(w_qkv, x, nullptr, nullptr, nullptr, /*flags=*/1);
    flash_attn<<<dim3(32, 8), 256, 53248>>>();
    gemm_tc<<<dim3(32, 4), 256, 71680>>>(w_out, nullptr, out, b_out, x, /*flags=*/2 | 8);
}

// round 12
// speedup vs baseline: 1.4941x; 1.4941x over previous
#include <cuda_runtime.h>
#include <cuda_bf16.h>
#include <cstdint>

#define NTOK 4096
#define CCH 512
#define NH 8
#define HD 64
#define MQKV 1536

// Scratch (device globals; no runtime allocation allowed)
__device__ float g_qkv[MQKV * NTOK];     // rows 0..511 q*scale (fp32); K/V rows unused now
__device__ uint32_t g_v[512 * 2048];     // V bf16x2: [channel(512)][jpair interleaved]
__device__ uint32_t g_k2[NH * 4096 * 32];// K bf16x2: [h][j(4096)][32 words, frag order]
__device__ float g_att[CCH * NTOK];      // [C, N] attention output (tf32-rounded)

__device__ __forceinline__ uint32_t f2tf32(float x) {
    uint32_t r;
    asm("cvt.rna.tf32.f32 %0, %1;" : "=r"(r) : "f"(x));
    return r;
}
__device__ __forceinline__ float f2tf32f(float x) {
    return __uint_as_float(f2tf32(x));
}
__device__ __forceinline__ uint32_t pack_bf16x2(float lo, float hi) {
    uint32_t r;
    asm("cvt.rn.bf16x2.f32 %0, %1, %2;" : "=r"(r) : "f"(hi), "f"(lo));
    return r;   // low 16 bits = lo, high = hi
}
__device__ __forceinline__ float exp2_fast(float x) {
    float y;
    asm("ex2.approx.ftz.f32 %0, %1;" : "=f"(y) : "f"(x));
    return y;
}
__device__ __forceinline__ void mma_tf32(float c[4], const uint32_t a[4],
                                         uint32_t b0, uint32_t b1) {
    asm volatile(
        "mma.sync.aligned.m16n8k8.row.col.f32.tf32.tf32.f32 "
        "{%0,%1,%2,%3}, {%4,%5,%6,%7}, {%8,%9}, {%0,%1,%2,%3};"
        : "+f"(c[0]), "+f"(c[1]), "+f"(c[2]), "+f"(c[3])
        : "r"(a[0]), "r"(a[1]), "r"(a[2]), "r"(a[3]), "r"(b0), "r"(b1));
}
__device__ __forceinline__ void mma_bf16(float c[4], const uint32_t a[4],
                                         uint32_t b0, uint32_t b1) {
    asm volatile(
        "mma.sync.aligned.m16n8k16.row.col.f32.bf16.bf16.f32 "
        "{%0,%1,%2,%3}, {%4,%5,%6,%7}, {%8,%9}, {%0,%1,%2,%3};"
        : "+f"(c[0]), "+f"(c[1]), "+f"(c[2]), "+f"(c[3])
        : "r"(a[0]), "r"(a[1]), "r"(a[2]), "r"(a[3]), "r"(b0), "r"(b1));
}
__device__ __forceinline__ uint32_t smem_u32(const void* p) {
    uint32_t a;
    asm("{ .reg .u64 t; cvta.to.shared.u64 t, %1; cvt.u32.u64 %0, t; }"
        : "=r"(a) : "l"(p));
    return a;
}
__device__ __forceinline__ void cp16(uint32_t dst, const void* src) {
    asm volatile("cp.async.ca.shared.global [%0], [%1], 16;" :: "r"(dst), "l"(src));
}
// bf16 index (0..63) within a 64-element g_k2 row for channel-dim position d.
// Word order matches the m16n8k16 B-fragment gather: within each d-chunk of 16
// (8 word-pairs), dpl -> word (dpl&3)*2 + (dpl>>2)  [bijection].
__device__ __forceinline__ int kpos(int d) {
    int dp = d >> 1, dpl = dp & 7, kc = dp >> 3;
    return kc * 16 + ((dpl & 3) * 2 + (dpl >> 2)) * 2 + (d & 1);
}

// ---------------------------------------------------------------------------
// Tensor-core GEMM, cp.async double-buffered.
// flags bit0 = qkv mode (Q scaled -> g_qkv, K bf16 -> g_k2, V bf16x2 -> g_v),
// bit1 = bias+residual, bit3 = B from g_att (else param B).
// ---------------------------------------------------------------------------
#define ASTR 36
#define BSTR 136
#define AFL (128 * ASTR)
#define BFL (32 * BSTR)

__global__ __launch_bounds__(256, 2) void gemm_tc(const float* __restrict__ Ain,
                                                  const float* __restrict__ Bin,
                                                  float* __restrict__ Cg,
                                                  const float* __restrict__ bias,
                                                  const float* __restrict__ res,
                                                  int flags) {
    extern __shared__ float smf[];
    const uint32_t sb = smem_u32(smf);

    const float* A = Ain;
    const float* B = (flags & 8) ? g_att : Bin;
    float* C = (flags & 1) ? g_qkv : Cg;

    const int t = threadIdx.x, lane = t & 31, w = t >> 5;
    const int g = lane >> 2, q4 = lane & 3;
    const int mw = (w >> 1) * 32;
    const int nw = (w & 1) * 64;
    const int m0 = blockIdx.y * 128, n0 = blockIdx.x * 128;

    float c[2][8][4] = {};

    int arow[4], acof[4], bk[4], bcof[4];
#pragma unroll
    for (int r = 0; r < 4; r++) {
        int cid = t + 256 * r;
        arow[r] = cid >> 3;  acof[r] = (cid & 7) * 4;
        bk[r]   = cid >> 5;  bcof[r] = (cid & 31) * 4;
    }

#pragma unroll
    for (int r = 0; r < 4; r++)
        cp16(sb + (arow[r] * ASTR + acof[r]) * 4,
             &A[(m0 + arow[r]) * 512 + acof[r]]);
#pragma unroll
    for (int r = 0; r < 4; r++)
        cp16(sb + 36864 + (bk[r] * BSTR + bcof[r]) * 4,
             &B[bk[r] * NTOK + n0 + bcof[r]]);
    asm volatile("cp.async.commit_group;" ::: "memory");

    for (int it = 0; it < 16; it++) {
        const int cur = it & 1;
        asm volatile("cp.async.wait_group 0;" ::: "memory");
        __syncthreads();

        if (it < 15) {
            const int k0 = (it + 1) * 32;
            const uint32_t ad = sb + ((cur ^ 1) ? 18432u : 0u);
            const uint32_t bd = sb + 36864 + ((cur ^ 1) ? 17408u : 0u);
#pragma unroll
            for (int r = 0; r < 4; r++)
                cp16(ad + (arow[r] * ASTR + acof[r]) * 4,
                     &A[(m0 + arow[r]) * 512 + k0 + acof[r]]);
#pragma unroll
            for (int r = 0; r < 4; r++)
                cp16(bd + (bk[r] * BSTR + bcof[r]) * 4,
                     &B[(k0 + bk[r]) * NTOK + n0 + bcof[r]]);
            asm volatile("cp.async.commit_group;" ::: "memory");
        }

        const float* As = smf + cur * AFL;
        const float* Bs = smf + 2 * AFL + cur * BFL;
#pragma unroll
        for (int kk = 0; kk < 32; kk += 8) {
            uint32_t af[2][4], bf[8][2];
#pragma unroll
            for (int mt = 0; mt < 2; mt++) {
                int am = (mw + g + mt * 16) * ASTR + kk + q4;
                af[mt][0] = __float_as_uint(As[am]);
                af[mt][1] = __float_as_uint(As[am + 8 * ASTR]);
                af[mt][2] = __float_as_uint(As[am + 4]);
                af[mt][3] = __float_as_uint(As[am + 8 * ASTR + 4]);
            }
            int br = (kk + q4) * BSTR + nw + g;
#pragma unroll
            for (int jt = 0; jt < 8; jt++) {
                bf[jt][0] = __float_as_uint(Bs[br + jt * 8]);
                bf[jt][1] = __float_as_uint(Bs[br + 4 * BSTR + jt * 8]);
            }
#pragma unroll
            for (int mt = 0; mt < 2; mt++)
#pragma unroll
                for (int jt = 0; jt < 8; jt++)
                    mma_tf32(c[mt][jt], af[mt], bf[jt][0], bf[jt][1]);
        }
    }

    const int mode = (flags & 1) ? (m0 >> 9) : 3;   // 0=Q 1=K 2=V 3=generic
    if (mode == 1) {
        // K -> g_k2: bf16 scatter in fragment word order [h][j][64 bf16]
        __nv_bfloat16* kb2 = (__nv_bfloat16*)g_k2;
#pragma unroll
        for (int mt = 0; mt < 2; mt++) {
#pragma unroll
            for (int jt = 0; jt < 8; jt++) {
                int ch = m0 - 512 + mw + mt * 16 + g;   // channel 0..511
                int h2 = ch >> 6;                        // ch and ch+8 share h2
                int d  = ch & 63;
                int j  = n0 + nw + jt * 8 + q4 * 2;
                int base0 = (h2 * 4096 + j) * 64;
                kb2[base0 + kpos(d)]          = __float2bfloat16(c[mt][jt][0]);
                kb2[base0 + 64 + kpos(d)]     = __float2bfloat16(c[mt][jt][1]);
                kb2[base0 + kpos(d + 8)]      = __float2bfloat16(c[mt][jt][2]);
                kb2[base0 + 64 + kpos(d + 8)] = __float2bfloat16(c[mt][jt][3]);
            }
        }
        return;
    }
    if (mode == 2) {
#pragma unroll
        for (int mt = 0; mt < 2; mt++) {
#pragma unroll
            for (int jt = 0; jt < 8; jt++) {
                int row = m0 + mw + mt * 16 + g - 1024;
                int jp = (n0 + nw + jt * 8 + q4 * 2) >> 1;
                g_v[row * 2048 + jp]       = pack_bf16x2(c[mt][jt][0], c[mt][jt][1]);
                g_v[(row + 8) * 2048 + jp] = pack_bf16x2(c[mt][jt][2], c[mt][jt][3]);
            }
        }
        return;
    }
    // Q scale folds hd^-0.5 * log2(e)
    const float sc = (mode == 0) ? 0.18033688011112042f : 1.0f;
#pragma unroll
    for (int mt = 0; mt < 2; mt++) {
#pragma unroll
        for (int jt = 0; jt < 8; jt++) {
            int row = m0 + mw + mt * 16 + g;
            int col = n0 + nw + jt * 8 + q4 * 2;
            float2 lo = make_float2(c[mt][jt][0] * sc, c[mt][jt][1] * sc);
            float2 hi = make_float2(c[mt][jt][2] * sc, c[mt][jt][3] * sc);
            if (flags & 2) {
                float b0v = bias[row], b1v = bias[row + 8];
                float2 r0 = *(const float2*)&res[row * NTOK + col];
                float2 r1 = *(const float2*)&res[(row + 8) * NTOK + col];
                lo.x += b0v + r0.x; lo.y += b0v + r0.y;
                hi.x += b1v + r1.x; hi.y += b1v + r1.y;
            }
            *(float2*)&C[row * NTOK + col] = lo;
            *(float2*)&C[(row + 8) * NTOK + col] = hi;
        }
    }
}

// ---------------------------------------------------------------------------
// Flash attention: all-bf16 tensor path.
// S = Q K^T via m16n8k16.bf16 (32 mma/warp-iter); PV m16n8k16.bf16 (proven).
// K smem: rows j (stride 40 words), word order pre-packed by gemm (g_k2) —
// B-frag load line is byte-isomorphic to the proven V load.
// Double-buffered K/V, one sync/iter. Smem: 2x10KB + 2x10KB = 40960 B.
// ---------------------------------------------------------------------------
__global__ __launch_bounds__(256, 2) void flash_attn() {
    extern __shared__ char sm[];
    uint32_t* Kh = (uint32_t*)sm;                  // [2][2560] bf16x2
    uint32_t* Vf = (uint32_t*)(sm + 20480);        // [2][2560] bf16x2

    const int t = threadIdx.x;
    const int w = t >> 5;
    const int lane = t & 31;
    const int g = lane >> 2;
    const int q4 = lane & 3;
    const int i0 = blockIdx.x * 128;
    const int h  = blockIdx.y;

    // ---- Q fragments (bf16 A-frags; pattern validated against proven Pa)
    uint32_t Qa[4][4];
    {
        const float* qb = g_qkv + (h * HD) * NTOK + i0 + w * 16 + g;
#pragma unroll
        for (int kc = 0; kc < 4; kc++) {
            int d0 = kc * 16 + q4 * 2;
            Qa[kc][0] = pack_bf16x2(qb[d0 * NTOK],           qb[(d0 + 1) * NTOK]);
            Qa[kc][1] = pack_bf16x2(qb[d0 * NTOK + 8],       qb[(d0 + 1) * NTOK + 8]);
            Qa[kc][2] = pack_bf16x2(qb[(d0 + 8) * NTOK],     qb[(d0 + 9) * NTOK]);
            Qa[kc][3] = pack_bf16x2(qb[(d0 + 8) * NTOK + 8], qb[(d0 + 9) * NTOK + 8]);
        }
    }

    // ---- staging constants
    // K: 64 rows x 8 uint4-chunks per tile; thread handles chunks t and t+256
    const uint32_t* srcK2 = g_k2 + (h * 4096) * 32;
    const int rK = t >> 3;              // rows rK and rK+32
    const int wK = (t & 7) * 4;         // word offset within row
    // V (unchanged, proven)
    const uint32_t* srcV = g_v + (h * HD + w) * 2048 + lane;
    const int dVbase = w * 40 + (lane >> 3) * 8 + (lane & 3) * 2 + ((lane >> 2) & 1);

    // ---- prologue: stage tile 0 into buffer 0
    {
        uint4 k0 = *(const uint4*)(srcK2 + rK * 32 + wK);
        uint4 k1 = *(const uint4*)(srcK2 + (rK + 32) * 32 + wK);
        *(uint4*)(Kh + rK * 40 + wK) = k0;
        *(uint4*)(Kh + (rK + 32) * 40 + wK) = k1;
        uint32_t vr[8];
#pragma unroll
        for (int it = 0; it < 8; it++) vr[it] = srcV[it * 16384];
#pragma unroll
        for (int it = 0; it < 8; it++) Vf[dVbase + 320 * it] = vr[it];
    }
    __syncthreads();

    float O[8][4] = {};
    float l0 = 0.f, l1 = 0.f;     // per-lane partials; reduced after the loop

    for (int kt = 0; kt < 64; kt++) {
        const int cur = kt & 1;

        // ---- stage tile kt+1 into other buffer (transient regs)
        if (kt < 63) {
            const int j0 = (kt + 1) * 64;
            uint32_t* Kd = Kh + (cur ^ 1) * 2560;
            uint4 k0 = *(const uint4*)(srcK2 + (j0 + rK) * 32 + wK);
            uint4 k1 = *(const uint4*)(srcK2 + (j0 + rK + 32) * 32 + wK);
            *(uint4*)(Kd + rK * 40 + wK) = k0;
            *(uint4*)(Kd + (rK + 32) * 40 + wK) = k1;
            const uint32_t* pv = srcV + (kt + 1) * 32;
            uint32_t* Vd = Vf + (cur ^ 1) * 2560;
            uint32_t vr[8];
#pragma unroll
            for (int it = 0; it < 8; it++) vr[it] = pv[it * 16384];
#pragma unroll
            for (int it = 0; it < 8; it++) Vd[dVbase + 320 * it] = vr[it];
        }

        // ---- S = Q K^T (bf16 m16n8k16); B-load isomorphic to proven V-load
        const uint32_t* Kc = Kh + cur * 2560;
        float S[8][4] = {};
#pragma unroll
        for (int kc = 0; kc < 4; kc++) {
#pragma unroll
            for (int jt = 0; jt < 8; jt++) {
                uint2 b = *(const uint2*)(Kc + (jt * 8 + g) * 40 + kc * 8 + q4 * 2);
                mma_bf16(S[jt], Qa[kc], b.x, b.y);
            }
        }

        // ---- no-max softmax (per-lane partial sums; shfl hoisted out of loop)
#pragma unroll
        for (int jt = 0; jt < 8; jt++) {
            S[jt][0] = exp2_fast(S[jt][0]);
            S[jt][1] = exp2_fast(S[jt][1]);
            S[jt][2] = exp2_fast(S[jt][2]);
            S[jt][3] = exp2_fast(S[jt][3]);
            l0 += S[jt][0] + S[jt][1];
            l1 += S[jt][2] + S[jt][3];
        }

        // ---- O += P V (bf16), C-frag -> A-frag register reuse (proven)
        const uint32_t* Vc = Vf + cur * 2560;
#pragma unroll
        for (int kc2 = 0; kc2 < 4; kc2++) {
            uint32_t Pa[4];
            Pa[0] = pack_bf16x2(S[2 * kc2][0],     S[2 * kc2][1]);
            Pa[1] = pack_bf16x2(S[2 * kc2][2],     S[2 * kc2][3]);
            Pa[2] = pack_bf16x2(S[2 * kc2 + 1][0], S[2 * kc2 + 1][1]);
            Pa[3] = pack_bf16x2(S[2 * kc2 + 1][2], S[2 * kc2 + 1][3]);
#pragma unroll
            for (int nt = 0; nt < 8; nt++) {
                uint2 bv = *(const uint2*)(Vc + (nt * 8 + g) * 40 + kc2 * 8 + q4 * 2);
                mma_bf16(O[nt], Pa, bv.x, bv.y);
            }
        }
        __syncthreads();
    }

    // ---- final l reduction (hoisted; sum is linear)
    l0 += __shfl_xor_sync(0xffffffffu, l0, 1);
    l0 += __shfl_xor_sync(0xffffffffu, l0, 2);
    l1 += __shfl_xor_sync(0xffffffffu, l1, 1);
    l1 += __shfl_xor_sync(0xffffffffu, l1, 2);

    // ---- normalize + store (tf32-rounded for out-proj raw staging)
    float inv0 = 1.0f / l0, inv1 = 1.0f / l1;
#pragma unroll
    for (int nt = 0; nt < 8; nt++) {
        float* p = g_att + (h * HD + nt * 8 + q4 * 2) * NTOK + i0 + w * 16 + g;
        p[0]        = f2tf32f(O[nt][0] * inv0);
        p[NTOK]     = f2tf32f(O[nt][1] * inv0);
        p[8]        = f2tf32f(O[nt][2] * inv1);
        p[NTOK + 8] = f2tf32f(O[nt][3] * inv1);
    }
}

extern "C" void kernel_launch(void* const* d_in, const int* in_sizes, int n_in,
                              void* d_out, int out_size) {
    const float* x     = (const float*)d_in[0];
    const float* w_qkv = (const float*)d_in[1];
    const float* w_out = (const float*)d_in[2];
    const float* b_out = (const float*)d_in[3];
    float* out = (float*)d_out;

    cudaFuncSetAttribute(flash_attn, cudaFuncAttributeMaxDynamicSharedMemorySize, 40960);
    cudaFuncSetAttribute(gemm_tc, cudaFuncAttributeMaxDynamicSharedMemorySize, 71680);

    gemm_tc<<<dim3(32, 12), 256, 71680>>>(w_qkv, x, nullptr, nullptr, nullptr, /*flags=*/1);
    flash_attn<<<dim3(32, 8), 256, 40960>>>();
    gemm_tc<<<dim3(32, 4), 256, 71680>>>(w_out, nullptr, out, b_out, x, /*flags=*/2 | 8);
}